// round 5
// baseline (speedup 1.0000x reference)
#include <cuda_runtime.h>

// Causal prefill attention, q,k,v,out: [B,H,L,D] fp32. B=2 H=16 L=2048 D=128.
// Flash-attention-2, tf32 mma.sync.m16n8k8, BR=BC=64, 4 warps/CTA, 2 CTAs/SM.
// P (softmax probs) relaid out C-fragment -> A-fragment via quad shuffles (no smem).

namespace {
constexpr int kL = 2048, kD = 128;
constexpr int BR = 64, BC = 64, NTHR = 128;
constexpr int QSTR = 132;   // %32==4 -> conflict-free A/B fragment LDS
constexpr int KSTR = 132;
constexpr int VSTR = 136;   // %32==8 -> conflict-free V B-fragment LDS
// (1/sqrt(128)) * log2(e): softmax in base-2, exp = single MUFU EX2
constexpr float kScaleLog2 = 0.12751745210670913f;
}

__device__ __forceinline__ float to_tf32(float x) {
    unsigned u;
    asm("cvt.rna.tf32.f32 %0, %1;" : "=r"(u) : "f"(x));
    return __uint_as_float(u);
}

__device__ __forceinline__ void mma_tf32(float c[4], const float a[4], float b0f, float b1f) {
    unsigned A0 = __float_as_uint(a[0]), A1 = __float_as_uint(a[1]);
    unsigned A2 = __float_as_uint(a[2]), A3 = __float_as_uint(a[3]);
    unsigned B0 = __float_as_uint(b0f), B1 = __float_as_uint(b1f);
    asm volatile(
        "mma.sync.aligned.m16n8k8.row.col.f32.tf32.tf32.f32 "
        "{%0,%1,%2,%3}, {%4,%5,%6,%7}, {%8,%9}, {%0,%1,%2,%3};\n"
        : "+f"(c[0]), "+f"(c[1]), "+f"(c[2]), "+f"(c[3])
        : "r"(A0), "r"(A1), "r"(A2), "r"(A3), "r"(B0), "r"(B1));
}

__global__ __launch_bounds__(NTHR, 2)
void fa_tf32_kernel(const float* __restrict__ gq,
                    const float* __restrict__ gk,
                    const float* __restrict__ gv,
                    float* __restrict__ gout) {
    extern __shared__ float sm[];
    float* Qs = sm;                      // [BR][QSTR]
    float* Ks = Qs + BR * QSTR;          // [BC][KSTR]
    float* Vs = Ks + BC * KSTR;          // [BC][VSTR]

    const int tid  = threadIdx.x;
    const int lane = tid & 31;
    const int wid  = tid >> 5;           // 0..3, warp owns 16 query rows
    const int g    = lane >> 2;          // 0..7
    const int lq   = lane & 3;           // 0..3
    const bool odd = (lq & 1);
    const int srcA = (lane & ~3) | (lq >> 1);   // quad-local shuffle sources
    const int srcB = srcA | 2;

    // heavy tiles first: reverse q-tile index to shrink the causal tail
    const int it = (int)gridDim.x - 1 - (int)blockIdx.x;
    const int bh = blockIdx.y;
    const size_t base = (size_t)bh * kL * kD;
    const int q0 = it * BR;

    // ---- stage Q (tf32-rounded) ----
    #pragma unroll
    for (int i = 0; i < (BR * kD / 4) / NTHR; ++i) {   // 16
        int lin = tid + i * NTHR;
        int r = lin >> 5, d4 = (lin & 31) << 2;
        float4 t = *reinterpret_cast<const float4*>(&gq[base + (size_t)(q0 + r) * kD + d4]);
        t.x = to_tf32(t.x); t.y = to_tf32(t.y); t.z = to_tf32(t.z); t.w = to_tf32(t.w);
        *reinterpret_cast<float4*>(&Qs[r * QSTR + d4]) = t;
    }

    float o[16][4];
    #pragma unroll
    for (int j = 0; j < 16; ++j) { o[j][0] = o[j][1] = o[j][2] = o[j][3] = 0.f; }
    float m0 = -1e30f, m1 = -1e30f;      // running max (log2 domain)
    float l0 = 0.f, l1 = 0.f;            // running denom

    const int Rg = wid * 16 + g;
    const int row0 = q0 + Rg, row1 = row0 + 8;

    const int njt = it + 1;
    for (int jt = 0; jt < njt; ++jt) {
        const int k0 = jt * BC;

        __syncthreads();   // prior iteration done with Ks/Vs
        #pragma unroll
        for (int i = 0; i < (BC * kD / 4) / NTHR; ++i) {   // 16
            int lin = tid + i * NTHR;
            int r = lin >> 5, d4 = (lin & 31) << 2;
            float4 tk = *reinterpret_cast<const float4*>(&gk[base + (size_t)(k0 + r) * kD + d4]);
            float4 tv = *reinterpret_cast<const float4*>(&gv[base + (size_t)(k0 + r) * kD + d4]);
            tk.x = to_tf32(tk.x); tk.y = to_tf32(tk.y); tk.z = to_tf32(tk.z); tk.w = to_tf32(tk.w);
            tv.x = to_tf32(tv.x); tv.y = to_tf32(tv.y); tv.z = to_tf32(tv.z); tv.w = to_tf32(tv.w);
            *reinterpret_cast<float4*>(&Ks[r * KSTR + d4]) = tk;
            *reinterpret_cast<float4*>(&Vs[r * VSTR + d4]) = tv;
        }
        __syncthreads();

        // ---- GEMM1: S[16x64] = Q Kt (warp-local rows) ----
        float s[8][4];
        #pragma unroll
        for (int j = 0; j < 8; ++j) { s[j][0] = s[j][1] = s[j][2] = s[j][3] = 0.f; }

        #pragma unroll 4
        for (int kk = 0; kk < 16; ++kk) {
            float a[4];
            const float* qa = &Qs[Rg * QSTR + 8 * kk + lq];
            a[0] = qa[0];
            a[1] = qa[8 * QSTR];
            a[2] = qa[4];
            a[3] = qa[8 * QSTR + 4];
            #pragma unroll
            for (int j = 0; j < 8; ++j) {
                const float* kb = &Ks[(8 * j + g) * KSTR + 8 * kk + lq];
                mma_tf32(s[j], a, kb[0], kb[4]);
            }
        }

        // ---- scale (log2 domain) + causal mask (diagonal tile only) ----
        const bool diag = (jt == it);
        float t0 = -1e30f, t1 = -1e30f;
        #pragma unroll
        for (int j = 0; j < 8; ++j) {
            #pragma unroll
            for (int c = 0; c < 4; ++c) s[j][c] *= kScaleLog2;
            if (diag) {
                int col = k0 + 8 * j + 2 * lq;
                if (col     > row0) s[j][0] = -1e30f;
                if (col + 1 > row0) s[j][1] = -1e30f;
                if (col     > row1) s[j][2] = -1e30f;
                if (col + 1 > row1) s[j][3] = -1e30f;
            }
            t0 = fmaxf(t0, fmaxf(s[j][0], s[j][1]));
            t1 = fmaxf(t1, fmaxf(s[j][2], s[j][3]));
        }
        t0 = fmaxf(t0, __shfl_xor_sync(0xffffffffu, t0, 1));
        t0 = fmaxf(t0, __shfl_xor_sync(0xffffffffu, t0, 2));
        t1 = fmaxf(t1, __shfl_xor_sync(0xffffffffu, t1, 1));
        t1 = fmaxf(t1, __shfl_xor_sync(0xffffffffu, t1, 2));

        const float mn0 = fmaxf(m0, t0), mn1 = fmaxf(m1, t1);
        const float al0 = exp2f(m0 - mn0), al1 = exp2f(m1 - mn1);
        m0 = mn0; m1 = mn1;

        // exp, tf32-round in place (these regs are the P C-fragments)
        float rs0 = 0.f, rs1 = 0.f;
        #pragma unroll
        for (int j = 0; j < 8; ++j) {
            float p0 = to_tf32(exp2f(s[j][0] - mn0));
            float p1 = to_tf32(exp2f(s[j][1] - mn0));
            float p2 = to_tf32(exp2f(s[j][2] - mn1));
            float p3 = to_tf32(exp2f(s[j][3] - mn1));
            rs0 += p0 + p1;
            rs1 += p2 + p3;
            s[j][0] = p0; s[j][1] = p1; s[j][2] = p2; s[j][3] = p3;
        }
        rs0 += __shfl_xor_sync(0xffffffffu, rs0, 1);
        rs0 += __shfl_xor_sync(0xffffffffu, rs0, 2);
        rs1 += __shfl_xor_sync(0xffffffffu, rs1, 1);
        rs1 += __shfl_xor_sync(0xffffffffu, rs1, 2);
        l0 = l0 * al0 + rs0;
        l1 = l1 * al1 + rs1;
        #pragma unroll
        for (int j = 0; j < 16; ++j) {
            o[j][0] *= al0; o[j][1] *= al0;
            o[j][2] *= al1; o[j][3] *= al1;
        }

        // ---- GEMM2: O[16x128] += P V. P C-frag -> A-frag via quad shuffles ----
        #pragma unroll 2
        for (int kk = 0; kk < 8; ++kk) {
            float u0 = __shfl_sync(0xffffffffu, s[kk][0], srcA);
            float u1 = __shfl_sync(0xffffffffu, s[kk][1], srcA);
            float w0 = __shfl_sync(0xffffffffu, s[kk][2], srcA);
            float w1 = __shfl_sync(0xffffffffu, s[kk][3], srcA);
            float v0 = __shfl_sync(0xffffffffu, s[kk][0], srcB);
            float v1 = __shfl_sync(0xffffffffu, s[kk][1], srcB);
            float x0 = __shfl_sync(0xffffffffu, s[kk][2], srcB);
            float x1 = __shfl_sync(0xffffffffu, s[kk][3], srcB);
            float a[4];
            a[0] = odd ? u1 : u0;   // P[g   ][8kk+lq]
            a[1] = odd ? w1 : w0;   // P[g+8 ][8kk+lq]
            a[2] = odd ? v1 : v0;   // P[g   ][8kk+lq+4]
            a[3] = odd ? x1 : x0;   // P[g+8 ][8kk+lq+4]
            #pragma unroll
            for (int j = 0; j < 16; ++j) {
                const float* vb = &Vs[(8 * kk + lq) * VSTR + 8 * j + g];
                mma_tf32(o[j], a, vb[0], vb[4 * VSTR]);
            }
        }
    }

    // ---- finalize: divide by l, write out ----
    const float inv0 = 1.0f / l0;
    const float inv1 = 1.0f / l1;
    const size_t r0off = base + (size_t)row0 * kD;
    const size_t r1off = base + (size_t)row1 * kD;
    #pragma unroll
    for (int j = 0; j < 16; ++j) {
        float2 w0; w0.x = o[j][0] * inv0; w0.y = o[j][1] * inv0;
        float2 w1; w1.x = o[j][2] * inv1; w1.y = o[j][3] * inv1;
        *reinterpret_cast<float2*>(&gout[r0off + 8 * j + 2 * lq]) = w0;
        *reinterpret_cast<float2*>(&gout[r1off + 8 * j + 2 * lq]) = w1;
    }
}

extern "C" void kernel_launch(void* const* d_in, const int* in_sizes, int n_in,
                              void* d_out, int out_size) {
    (void)in_sizes; (void)n_in; (void)out_size;
    const float* q = (const float*)d_in[0];
    const float* k = (const float*)d_in[1];
    const float* v = (const float*)d_in[2];
    float* out = (float*)d_out;

    const size_t smem = (size_t)(BR * QSTR + BC * KSTR + BC * VSTR) * sizeof(float); // 102400 B
    cudaFuncSetAttribute(fa_tf32_kernel,
                         cudaFuncAttributeMaxDynamicSharedMemorySize, (int)smem);

    dim3 grid(kL / BR, 32);   // 32 q-tiles x (B*H=32)
    fa_tf32_kernel<<<grid, NTHR, smem>>>(q, k, v, out);
}